// round 4
// baseline (speedup 1.0000x reference)
#include <cuda_runtime.h>
#include <cstdint>

#define N_NODES 200000
#define NBUCK   2048          // dst buckets: 2048 * 98 = 200704 >= N
#define BSZ     98            // nodes per bucket (local id fits in 7 bits)
#define NSTR    5             // padded per-node stride in accumulator (coprime to 32)
#define NREP    8             // per-warp accumulator replicas
#define NBB     512           // blocks for binning build
#define CSR_CAP 12800000

// ---------- device scratch (no allocs allowed) ----------
__device__ float4   g_z0[N_NODES];          // [x - mean, 1]
__device__ float4   g_a1[N_NODES];          // A z0   (xyz = g1, w = deg)
__device__ float4   g_a2[N_NODES];          // A a1   (xyz = g2, w = d2)
__device__ float4   g_a3[N_NODES];          // A a2
__device__ float    g_sum[3];
__device__ float    g_mat[36];              // Q1,Q2,Q3,u,v,b3
__device__ int      g_counts[NBB * NBUCK];  // per-block per-bucket histogram
__device__ int      g_base[NBB * NBUCK];    // exclusive scan over blocks (per bucket)
__device__ int      g_tot[NBUCK];
__device__ int      g_boffs[NBUCK + 1];
__device__ unsigned g_csr[CSR_CAP];         // packed: src | (local<<18), bucket-sorted

// ---------- tiny kernels ----------
__global__ void k_zero() {
    if (threadIdx.x < 3) g_sum[threadIdx.x] = 0.f;
}

__global__ void k_mean(const float* __restrict__ x) {
    int n = blockIdx.x * blockDim.x + threadIdx.x;
    float a = 0.f, b = 0.f, c = 0.f;
    if (n < N_NODES) { a = x[3*n]; b = x[3*n+1]; c = x[3*n+2]; }
    #pragma unroll
    for (int o = 16; o > 0; o >>= 1) {
        a += __shfl_down_sync(0xffffffffu, a, o);
        b += __shfl_down_sync(0xffffffffu, b, o);
        c += __shfl_down_sync(0xffffffffu, c, o);
    }
    __shared__ float sa[8], sb[8], sc[8];
    int w = threadIdx.x >> 5, l = threadIdx.x & 31;
    if (l == 0) { sa[w] = a; sb[w] = b; sc[w] = c; }
    __syncthreads();
    if (threadIdx.x == 0) {
        float ta = 0.f, tb = 0.f, tc = 0.f;
        #pragma unroll
        for (int i = 0; i < 8; i++) { ta += sa[i]; tb += sb[i]; tc += sc[i]; }
        atomicAdd(&g_sum[0], ta);
        atomicAdd(&g_sum[1], tb);
        atomicAdd(&g_sum[2], tc);
    }
}

__global__ void k_center(const float* __restrict__ x) {
    int n = blockIdx.x * blockDim.x + threadIdx.x;
    if (n >= N_NODES) return;
    const float inv = 1.0f / (float)N_NODES;
    float m0 = g_sum[0] * inv, m1 = g_sum[1] * inv, m2 = g_sum[2] * inv;
    g_z0[n] = make_float4(x[3*n] - m0, x[3*n+1] - m1, x[3*n+2] - m2, 1.0f);
}

// Collapsed 3x3 matrices (round-0 derivation)
__global__ void k_mat(const float* __restrict__ w1, const float* __restrict__ b1,
                      const float* __restrict__ w2, const float* __restrict__ b2,
                      const float* __restrict__ w3, const float* __restrict__ b3) {
    __shared__ float T[3][50];   // T = W3a * W2a
    int tid = threadIdx.x;
    if (tid < 150) {
        int i = tid / 50, k = tid % 50;
        float s = 0.f;
        for (int j = 0; j < 50; j++) s += w3[i*103 + j] * w2[j*53 + k];
        T[i][k] = s;
    }
    __syncthreads();
    if (tid < 9) {                       // Q3 = T * W1
        int i = tid / 3, c = tid % 3;
        float s = 0.f;
        for (int k = 0; k < 50; k++) s += T[i][k] * w1[k*3 + c];
        g_mat[18 + tid] = s;
    } else if (tid < 18) {               // Q2 = W3a*W2b + W3b*W1
        int q = tid - 9; int i = q / 3, c = q % 3;
        float s = 0.f;
        for (int j = 0; j < 50; j++) s += w3[i*103 + j] * w2[j*53 + 50 + c];
        for (int k = 0; k < 50; k++) s += w3[i*103 + 50 + k] * w1[k*3 + c];
        g_mat[9 + q] = s;
    } else if (tid < 27) {               // Q1 = W3c
        int q = tid - 18; int i = q / 3, c = q % 3;
        g_mat[q] = w3[i*103 + 100 + c];
    } else if (tid < 30) {               // u = T * b1
        int i = tid - 27;
        float s = 0.f;
        for (int k = 0; k < 50; k++) s += T[i][k] * b1[k];
        g_mat[27 + i] = s;
    } else if (tid < 33) {               // v = W3a*b2 + W3b*b1
        int i = tid - 30;
        float s = 0.f;
        for (int j = 0; j < 50; j++) s += w3[i*103 + j] * b2[j];
        for (int k = 0; k < 50; k++) s += w3[i*103 + 50 + k] * b1[k];
        g_mat[30 + i] = s;
    } else if (tid < 36) {
        g_mat[tid] = b3[tid - 33];
    }
}

// ---------- build: bin edges by destination bucket (single stage) ----------
__global__ void k_bhist(const int* __restrict__ ei, int E) {
    __shared__ int sh[NBUCK];
    int tid = threadIdx.x, blk = blockIdx.x;
    for (int i = tid; i < NBUCK; i += 256) sh[i] = 0;
    __syncthreads();
    int CH = (E + NBB - 1) / NBB;
    int st = blk * CH, en = min(E, st + CH);
    for (int e = st + tid; e < en; e += 256) {
        int d = __ldg(ei + E + e);
        atomicAdd(&sh[d / BSZ], 1);
    }
    __syncthreads();
    for (int i = tid; i < NBUCK; i += 256) g_counts[blk * NBUCK + i] = sh[i];
}

// Per bucket: exclusive scan over the NBB block counts -> g_base, totals -> g_tot
__global__ void k_scanA() {
    int warp = (blockIdx.x * blockDim.x + threadIdx.x) >> 5;
    int lane = threadIdx.x & 31;
    if (warp >= NBUCK) return;
    int carry = 0;
    #pragma unroll
    for (int k = 0; k < NBB / 32; k++) {
        int idx = k * 32 + lane;
        int v = g_counts[idx * NBUCK + warp];
        int s = v;
        #pragma unroll
        for (int o = 1; o < 32; o <<= 1) {
            int t = __shfl_up_sync(0xffffffffu, s, o);
            if (lane >= o) s += t;
        }
        g_base[idx * NBUCK + warp] = carry + s - v;
        carry += __shfl_sync(0xffffffffu, s, 31);
    }
    if (lane == 0) g_tot[warp] = carry;
}

// Exclusive scan of the NBUCK totals -> g_boffs (single block, 1024 threads)
__global__ void k_scanB() {
    __shared__ int sm[1024];
    int t = threadIdx.x;
    int a = g_tot[2*t], b = g_tot[2*t + 1];
    sm[t] = a + b;
    __syncthreads();
    for (int o = 1; o < 1024; o <<= 1) {
        int v = (t >= o) ? sm[t - o] : 0;
        __syncthreads();
        sm[t] += v;
        __syncthreads();
    }
    int incl = sm[t];
    int excl = incl - (a + b);
    g_boffs[2*t]     = excl;
    g_boffs[2*t + 1] = excl + a;
    if (t == 1023) g_boffs[2048] = incl;
}

// Scatter packed (src | local<<18) to bucket-sorted order; ranks from smem
// cursors seeded with g_base + g_boffs -> no global atomics. Per-block cursor
// positions within a bucket are consecutive, so L2 write-merges the 4B stores.
__global__ void k_bscatter(const int* __restrict__ ei, int E) {
    __shared__ int cur[NBUCK];
    int tid = threadIdx.x, blk = blockIdx.x;
    for (int i = tid; i < NBUCK; i += 256)
        cur[i] = g_base[blk * NBUCK + i] + g_boffs[i];
    __syncthreads();
    int CH = (E + NBB - 1) / NBB;
    int st = blk * CH, en = min(E, st + CH);
    for (int e = st + tid; e < en; e += 256) {
        int s = __ldg(ei + e);
        int d = __ldg(ei + E + e);
        int b = d / BSZ;
        int l = d - b * BSZ;
        int pos = atomicAdd(&cur[b], 1);
        g_csr[pos] = (unsigned)s | ((unsigned)l << 18);
    }
}

// ---------- one aggregation pass ----------
// One block per bucket; per-warp-replicated padded smem accumulators, then
// cross-replica reduce and a single coalesced float4 store per node.
__global__ void __launch_bounds__(256) k_pass(const float4* __restrict__ in,
                                              float4* __restrict__ out) {
    __shared__ float acc[NREP][BSZ * NSTR];   // 8 x 490 floats = 15.7 KB
    int tid = threadIdx.x, b = blockIdx.x;
    for (int i = tid; i < NREP * BSZ * NSTR; i += 256) ((float*)acc)[i] = 0.f;
    __syncthreads();
    int s0 = g_boffs[b], s1 = g_boffs[b + 1];
    float* my = acc[tid >> 5];
    int e = s0 + tid;
    for (; e + 7 * 256 < s1; e += 8 * 256) {
        unsigned w[8]; float4 v[8];
        #pragma unroll
        for (int j = 0; j < 8; j++) w[j] = g_csr[e + j * 256];
        #pragma unroll
        for (int j = 0; j < 8; j++) v[j] = __ldg(&in[w[j] & 0x3FFFFu]);
        #pragma unroll
        for (int j = 0; j < 8; j++) {
            unsigned l = (w[j] >> 18) * NSTR;
            atomicAdd(&my[l + 0], v[j].x);
            atomicAdd(&my[l + 1], v[j].y);
            atomicAdd(&my[l + 2], v[j].z);
            atomicAdd(&my[l + 3], v[j].w);
        }
    }
    for (; e < s1; e += 256) {
        unsigned w = g_csr[e];
        float4 v = __ldg(&in[w & 0x3FFFFu]);
        unsigned l = (w >> 18) * NSTR;
        atomicAdd(&my[l + 0], v.x);
        atomicAdd(&my[l + 1], v.y);
        atomicAdd(&my[l + 2], v.z);
        atomicAdd(&my[l + 3], v.w);
    }
    __syncthreads();
    for (int l = tid; l < BSZ; l += 256) {
        int node = b * BSZ + l;
        if (node < N_NODES) {
            float sx = 0.f, sy = 0.f, sz = 0.f, sw = 0.f;
            #pragma unroll
            for (int r = 0; r < NREP; r++) {
                sx += acc[r][l*NSTR + 0];
                sy += acc[r][l*NSTR + 1];
                sz += acc[r][l*NSTR + 2];
                sw += acc[r][l*NSTR + 3];
            }
            out[node] = make_float4(sx, sy, sz, sw);
        }
    }
}

__global__ void k_final(const float* __restrict__ x, float* __restrict__ out) {
    int n = blockIdx.x * blockDim.x + threadIdx.x;
    if (n >= N_NODES) return;
    int r = n % 40;
    if (n < 1960 && (r < 14 || (r >= 25 && r < 39))) {
        out[3*n]   = x[3*n];
        out[3*n+1] = x[3*n+1];
        out[3*n+2] = x[3*n+2];
        return;
    }
    float4 a1 = g_a1[n], a2 = g_a2[n], a3 = g_a3[n];
    const float inv = 1.0f / (float)N_NODES;
    #pragma unroll
    for (int c = 0; c < 3; c++) {
        float s = g_mat[33 + c] + g_sum[c] * inv;          // b3 + mean
        s += a1.x * g_mat[c*3 + 0] + a1.y * g_mat[c*3 + 1] + a1.z * g_mat[c*3 + 2];
        s += a2.x * g_mat[9 + c*3 + 0] + a2.y * g_mat[9 + c*3 + 1] + a2.z * g_mat[9 + c*3 + 2];
        s += a3.x * g_mat[18 + c*3 + 0] + a3.y * g_mat[18 + c*3 + 1] + a3.z * g_mat[18 + c*3 + 2];
        s += a2.w * g_mat[27 + c];   // d2 * u
        s += a1.w * g_mat[30 + c];   // deg * v
        out[3*n + c] = s;
    }
}

// ---------- launch ----------
extern "C" void kernel_launch(void* const* d_in, const int* in_sizes, int n_in,
                              void* d_out, int out_size) {
    const float* x   = (const float*)d_in[0];
    const int*   ei  = (const int*)d_in[1];
    const float* w1  = (const float*)d_in[5];   // c1_w2
    const float* b1  = (const float*)d_in[6];   // c1_b2
    const float* w2  = (const float*)d_in[9];   // c2_w2
    const float* b2  = (const float*)d_in[10];  // c2_b2
    const float* w3  = (const float*)d_in[13];  // c3_w2
    const float* b3  = (const float*)d_in[14];  // c3_b2
    float* out = (float*)d_out;

    int E = in_sizes[1] / 2;
    if (E > CSR_CAP) E = CSR_CAP;

    float4 *z0p, *a1p, *a2p, *a3p;
    cudaGetSymbolAddress((void**)&z0p, g_z0);
    cudaGetSymbolAddress((void**)&a1p, g_a1);
    cudaGetSymbolAddress((void**)&a2p, g_a2);
    cudaGetSymbolAddress((void**)&a3p, g_a3);

    const int BT = 256;
    int node_grid = (N_NODES + BT - 1) / BT;

    k_zero<<<1, 32>>>();
    k_mat<<<1, 192>>>(w1, b1, w2, b2, w3, b3);
    k_mean<<<node_grid, BT>>>(x);
    k_center<<<node_grid, BT>>>(x);

    k_bhist<<<NBB, BT>>>(ei, E);
    k_scanA<<<NBUCK / 8, BT>>>();
    k_scanB<<<1, 1024>>>();
    k_bscatter<<<NBB, BT>>>(ei, E);

    k_pass<<<NBUCK, BT>>>(z0p, a1p);
    k_pass<<<NBUCK, BT>>>(a1p, a2p);
    k_pass<<<NBUCK, BT>>>(a2p, a3p);

    k_final<<<node_grid, BT>>>(x, out);
}

// round 5
// speedup vs baseline: 1.6810x; 1.6810x over previous
#include <cuda_runtime.h>
#include <cstdint>

#define N_NODES 200000

// ---------- device scratch (no allocs allowed) ----------
__device__ float4 g_z0[N_NODES];   // [x, 1] (UNcentered; centering folded into pass2/final)
__device__ float4 g_a1[N_NODES];   // A z0u   (xyz = A x, w = deg)
__device__ float4 g_a2[N_NODES];   // A a1c   (xyz = g2, w = d2)
__device__ float4 g_a3[N_NODES];   // A a2
__device__ float  g_sum[3];        // column sums of x
__device__ float  g_mat[36];       // Q1,Q2,Q3,u,v,b3

__device__ __forceinline__ void red_add_v4(float4* p, float4 v) {
    asm volatile("red.global.add.v4.f32 [%0], {%1, %2, %3, %4};"
                 :: "l"(p), "f"(v.x), "f"(v.y), "f"(v.z), "f"(v.w)
                 : "memory");
}

__global__ void k_zero() {
    if (threadIdx.x < 3) g_sum[threadIdx.x] = 0.f;
}

// One node-grid kernel: build z0u=(x,1), zero accumulators, column-sum partials.
__global__ void k_prep(const float* __restrict__ x) {
    int n = blockIdx.x * blockDim.x + threadIdx.x;
    float a = 0.f, b = 0.f, c = 0.f;
    float4 z = make_float4(0.f, 0.f, 0.f, 0.f);
    if (n < N_NODES) {
        a = x[3*n]; b = x[3*n+1]; c = x[3*n+2];
        g_z0[n] = make_float4(a, b, c, 1.0f);
        g_a1[n] = z; g_a2[n] = z; g_a3[n] = z;
    }
    #pragma unroll
    for (int o = 16; o > 0; o >>= 1) {
        a += __shfl_down_sync(0xffffffffu, a, o);
        b += __shfl_down_sync(0xffffffffu, b, o);
        c += __shfl_down_sync(0xffffffffu, c, o);
    }
    __shared__ float sa[8], sb[8], sc[8];
    int w = threadIdx.x >> 5, l = threadIdx.x & 31;
    if (l == 0) { sa[w] = a; sb[w] = b; sc[w] = c; }
    __syncthreads();
    if (threadIdx.x == 0) {
        float ta = 0.f, tb = 0.f, tc = 0.f;
        #pragma unroll
        for (int i = 0; i < 8; i++) { ta += sa[i]; tb += sb[i]; tc += sc[i]; }
        atomicAdd(&g_sum[0], ta);
        atomicAdd(&g_sum[1], tb);
        atomicAdd(&g_sum[2], tc);
    }
}

// Collapsed 3x3 matrices (round-0 derivation)
__global__ void k_mat(const float* __restrict__ w1, const float* __restrict__ b1,
                      const float* __restrict__ w2, const float* __restrict__ b2,
                      const float* __restrict__ w3, const float* __restrict__ b3) {
    __shared__ float T[3][50];   // T = W3a * W2a
    int tid = threadIdx.x;
    if (tid < 150) {
        int i = tid / 50, k = tid % 50;
        float s = 0.f;
        for (int j = 0; j < 50; j++) s += w3[i*103 + j] * w2[j*53 + k];
        T[i][k] = s;
    }
    __syncthreads();
    if (tid < 9) {                       // Q3 = T * W1
        int i = tid / 3, c = tid % 3;
        float s = 0.f;
        for (int k = 0; k < 50; k++) s += T[i][k] * w1[k*3 + c];
        g_mat[18 + tid] = s;
    } else if (tid < 18) {               // Q2 = W3a*W2b + W3b*W1
        int q = tid - 9; int i = q / 3, c = q % 3;
        float s = 0.f;
        for (int j = 0; j < 50; j++) s += w3[i*103 + j] * w2[j*53 + 50 + c];
        for (int k = 0; k < 50; k++) s += w3[i*103 + 50 + k] * w1[k*3 + c];
        g_mat[9 + q] = s;
    } else if (tid < 27) {               // Q1 = W3c
        int q = tid - 18; int i = q / 3, c = q % 3;
        g_mat[q] = w3[i*103 + 100 + c];
    } else if (tid < 30) {               // u = T * b1
        int i = tid - 27;
        float s = 0.f;
        for (int k = 0; k < 50; k++) s += T[i][k] * b1[k];
        g_mat[27 + i] = s;
    } else if (tid < 33) {               // v = W3a*b2 + W3b*b1
        int i = tid - 30;
        float s = 0.f;
        for (int j = 0; j < 50; j++) s += w3[i*103 + j] * b2[j];
        for (int k = 0; k < 50; k++) s += w3[i*103 + 50 + k] * b1[k];
        g_mat[30 + i] = s;
    } else if (tid < 36) {
        g_mat[tid] = b3[tid - 33];
    }
}

// One scatter-red pass over all edges, 8 edges/thread.
// On-the-fly centering: v.xyz -= v.w * (sums[c] * fscale). fscale=0 disables.
__global__ void __launch_bounds__(256)
k_scatter(const int* __restrict__ ei, int E,
          const float4* __restrict__ in, float4* __restrict__ out,
          const float* __restrict__ sums, float fscale) {
    float cx = __ldg(sums + 0) * fscale;
    float cy = __ldg(sums + 1) * fscale;
    float cz = __ldg(sums + 2) * fscale;
    int t = blockIdx.x * blockDim.x + threadIdx.x;
    int n8 = E >> 3;
    if (t < n8) {
        const int4* sp = (const int4*)ei;
        const int4* dp = (const int4*)(ei + E);
        int4 s0 = __ldcs(sp + 2*t),     s1 = __ldcs(sp + 2*t + 1);
        int4 d0 = __ldcs(dp + 2*t),     d1 = __ldcs(dp + 2*t + 1);
        float4 v[8];
        v[0] = __ldg(in + s0.x); v[1] = __ldg(in + s0.y);
        v[2] = __ldg(in + s0.z); v[3] = __ldg(in + s0.w);
        v[4] = __ldg(in + s1.x); v[5] = __ldg(in + s1.y);
        v[6] = __ldg(in + s1.z); v[7] = __ldg(in + s1.w);
        #pragma unroll
        for (int j = 0; j < 8; j++) {
            v[j].x -= v[j].w * cx;
            v[j].y -= v[j].w * cy;
            v[j].z -= v[j].w * cz;
        }
        red_add_v4(out + d0.x, v[0]); red_add_v4(out + d0.y, v[1]);
        red_add_v4(out + d0.z, v[2]); red_add_v4(out + d0.w, v[3]);
        red_add_v4(out + d1.x, v[4]); red_add_v4(out + d1.y, v[5]);
        red_add_v4(out + d1.z, v[6]); red_add_v4(out + d1.w, v[7]);
    } else {
        int rem = E & 7;
        int q = t - n8;
        if (q < rem) {
            int e = 8 * n8 + q;
            int s = __ldg(ei + e);
            int d = __ldg(ei + E + e);
            float4 v = __ldg(in + s);
            v.x -= v.w * cx; v.y -= v.w * cy; v.z -= v.w * cz;
            red_add_v4(out + d, v);
        }
    }
}

__global__ void k_final(const float* __restrict__ x, float* __restrict__ out) {
    int n = blockIdx.x * blockDim.x + threadIdx.x;
    if (n >= N_NODES) return;
    int r = n % 40;
    if (n < 1960 && (r < 14 || (r >= 25 && r < 39))) {
        out[3*n]   = x[3*n];
        out[3*n+1] = x[3*n+1];
        out[3*n+2] = x[3*n+2];
        return;
    }
    const float inv = 1.0f / (float)N_NODES;
    float m0 = g_sum[0] * inv, m1 = g_sum[1] * inv, m2 = g_sum[2] * inv;
    float4 a1 = g_a1[n], a2 = g_a2[n], a3 = g_a3[n];
    // a1 is RAW (A x, deg): center it here: g1 = a1.xyz - deg*mean
    float g1x = a1.x - a1.w * m0;
    float g1y = a1.y - a1.w * m1;
    float g1z = a1.z - a1.w * m2;
    float mean[3] = {m0, m1, m2};
    #pragma unroll
    for (int c = 0; c < 3; c++) {
        float s = g_mat[33 + c] + mean[c];                 // b3 + mean
        s += g1x  * g_mat[c*3 + 0] + g1y  * g_mat[c*3 + 1] + g1z  * g_mat[c*3 + 2];
        s += a2.x * g_mat[9 + c*3 + 0] + a2.y * g_mat[9 + c*3 + 1] + a2.z * g_mat[9 + c*3 + 2];
        s += a3.x * g_mat[18 + c*3 + 0] + a3.y * g_mat[18 + c*3 + 1] + a3.z * g_mat[18 + c*3 + 2];
        s += a2.w * g_mat[27 + c];   // d2 * u
        s += a1.w * g_mat[30 + c];   // deg * v
        out[3*n + c] = s;
    }
}

// ---------- launch ----------
extern "C" void kernel_launch(void* const* d_in, const int* in_sizes, int n_in,
                              void* d_out, int out_size) {
    const float* x   = (const float*)d_in[0];
    const int*   ei  = (const int*)d_in[1];
    const float* w1  = (const float*)d_in[5];   // c1_w2
    const float* b1  = (const float*)d_in[6];   // c1_b2
    const float* w2  = (const float*)d_in[9];   // c2_w2
    const float* b2  = (const float*)d_in[10];  // c2_b2
    const float* w3  = (const float*)d_in[13];  // c3_w2
    const float* b3  = (const float*)d_in[14];  // c3_b2
    float* out = (float*)d_out;

    int E = in_sizes[1] / 2;

    float4 *z0p, *a1p, *a2p, *a3p;
    float  *sump;
    cudaGetSymbolAddress((void**)&z0p, g_z0);
    cudaGetSymbolAddress((void**)&a1p, g_a1);
    cudaGetSymbolAddress((void**)&a2p, g_a2);
    cudaGetSymbolAddress((void**)&a3p, g_a3);
    cudaGetSymbolAddress((void**)&sump, g_sum);

    const int BT = 256;
    int node_grid = (N_NODES + BT - 1) / BT;
    int n_items = (E >> 3) + (E & 7);
    int edge_grid = (n_items + BT - 1) / BT;
    const float invN = 1.0f / (float)N_NODES;

    k_zero<<<1, 32>>>();
    k_prep<<<node_grid, BT>>>(x);
    k_mat<<<1, 192>>>(w1, b1, w2, b2, w3, b3);
    // pass1: z0u -> a1 (raw; no centering needed, fscale=0)
    k_scatter<<<edge_grid, BT>>>(ei, E, z0p, a1p, sump, 0.0f);
    // pass2: center a1 on the fly: v.xyz -= v.w * mean
    k_scatter<<<edge_grid, BT>>>(ei, E, a1p, a2p, sump, invN);
    // pass3: a2 already exact
    k_scatter<<<edge_grid, BT>>>(ei, E, a2p, a3p, sump, 0.0f);
    k_final<<<node_grid, BT>>>(x, out);
}